// round 1
// baseline (speedup 1.0000x reference)
#include <cuda_runtime.h>
#include <math.h>

// Problem constants
constexpr int Bb  = 2;
constexpr int Ll  = 2048;
constexpr int Dd  = 512;
constexpr int Hh  = 8;
constexpr int HD  = 64;
constexpr int DH  = 2048;
constexpr int MREL = 128;      // rel bias clip
constexpr int D3  = 3 * Dd;    // 1536
constexpr int BL  = Bb * Ll;   // 4096
constexpr long long XSIZE  = (long long)BL * Dd;            // 2,097,152
constexpr long long ATTN_N = (long long)Bb * Hh * Ll * Ll;  // 67,108,864

// Scratch (allocation-free rule: __device__ globals)
__device__ float g_h    [BL * Dd];      // LN output (reused for ln2)
__device__ float g_qkv  [BL * D3];      // fused qkv
__device__ float g_o    [BL * Dd];      // attention context (b,l,d)
__device__ float g_proj [BL * Dd];      // out-proj / ffn-out result
__device__ float g_x1   [BL * Dd];      // residual 1
__device__ float g_ab   [BL * 2 * DH];  // ffn_in output
__device__ float g_f    [BL * DH];      // geglu output

// ---------------- LayerNorm: one block per row of 512 ----------------
__global__ void ln_kernel(const float* __restrict__ x, const float* __restrict__ w,
                          const float* __restrict__ b, float* __restrict__ out) {
    int row = blockIdx.x;
    const float* xr = x + (long long)row * Dd;
    int t = threadIdx.x; // 256
    float v0 = xr[t], v1 = xr[t + 256];
    __shared__ float red[256];
    red[t] = v0 + v1;
    __syncthreads();
    #pragma unroll
    for (int o = 128; o > 0; o >>= 1) { if (t < o) red[t] += red[t + o]; __syncthreads(); }
    float mu = red[0] * (1.0f / Dd);
    __syncthreads();
    float d0 = v0 - mu, d1 = v1 - mu;
    red[t] = d0 * d0 + d1 * d1;
    __syncthreads();
    #pragma unroll
    for (int o = 128; o > 0; o >>= 1) { if (t < o) red[t] += red[t + o]; __syncthreads(); }
    float rstd = rsqrtf(red[0] * (1.0f / Dd) + 1e-5f);
    float* orow = out + (long long)row * Dd;
    orow[t]       = d0 * rstd * w[t]       + b[t];
    orow[t + 256] = d1 * rstd * w[t + 256] + b[t + 256];
}

// ---------------- Generic GEMM: C[M,N] = A[M,K] @ W[K,N] + bias ----------------
// BM=BN=64, BK=16, 256 threads, 4x4 microtile. All dims divide exactly.
__global__ void gemm_bias_kernel(const float* __restrict__ A, const float* __restrict__ W,
                                 const float* __restrict__ bias, float* __restrict__ C,
                                 int N, int K) {
    __shared__ float As[16][64];
    __shared__ float Bs[16][68];  // pad to dodge conflicts on 4-stride reads
    int bm = blockIdx.y * 64, bn = blockIdx.x * 64;
    int tid = threadIdx.x;
    int ty = tid >> 4, tx = tid & 15;
    float acc[4][4] = {};
    for (int k0 = 0; k0 < K; k0 += 16) {
        #pragma unroll
        for (int i = 0; i < 4; i++) {
            int idx = tid + i * 256;
            int m = idx >> 4, kk = idx & 15;
            As[kk][m] = A[(long long)(bm + m) * K + k0 + kk];
        }
        #pragma unroll
        for (int i = 0; i < 4; i++) {
            int idx = tid + i * 256;
            int kk = idx >> 6, n = idx & 63;
            Bs[kk][n] = W[(long long)(k0 + kk) * N + bn + n];
        }
        __syncthreads();
        #pragma unroll
        for (int kk = 0; kk < 16; kk++) {
            float a[4], bv[4];
            #pragma unroll
            for (int i = 0; i < 4; i++) a[i]  = As[kk][ty * 4 + i];
            #pragma unroll
            for (int j = 0; j < 4; j++) bv[j] = Bs[kk][tx * 4 + j];
            #pragma unroll
            for (int i = 0; i < 4; i++)
                #pragma unroll
                for (int j = 0; j < 4; j++) acc[i][j] += a[i] * bv[j];
        }
        __syncthreads();
    }
    #pragma unroll
    for (int i = 0; i < 4; i++) {
        long long m = bm + ty * 4 + i;
        #pragma unroll
        for (int j = 0; j < 4; j++) {
            int n = bn + tx * 4 + j;
            C[m * N + n] = acc[i][j] + bias[n];
        }
    }
}

// ---------------- Scores: S[b,h,q,k] = scale*(q.k) + rel_bias ----------------
// 64x64 output tile per block, full HD=64 depth in one shot.
__global__ void score_kernel(const float* __restrict__ qkv, const float* __restrict__ rel_bias,
                             float* __restrict__ attn) {
    int bh = blockIdx.z;
    int b = bh >> 3, h = bh & 7;
    int q0 = blockIdx.y * 64, k0 = blockIdx.x * 64;
    __shared__ float Qs[64][65];
    __shared__ float Ks[64][65];
    int tid = threadIdx.x;
    int ty = tid >> 4, tx = tid & 15;
    const long long baseQ = (long long)b * Ll * D3 + h * HD;
    const long long baseK = baseQ + Dd;
    #pragma unroll
    for (int i = 0; i < 16; i++) {
        int idx = tid + i * 256;
        int r = idx >> 6, d = idx & 63;
        Qs[r][d] = qkv[baseQ + (long long)(q0 + r) * D3 + d];
        Ks[r][d] = qkv[baseK + (long long)(k0 + r) * D3 + d];
    }
    __syncthreads();
    float acc[4][4] = {};
    #pragma unroll 8
    for (int d = 0; d < 64; d++) {
        float a[4], bv[4];
        #pragma unroll
        for (int i = 0; i < 4; i++) a[i]  = Qs[ty * 4 + i][d];
        #pragma unroll
        for (int j = 0; j < 4; j++) bv[j] = Ks[tx * 4 + j][d];
        #pragma unroll
        for (int i = 0; i < 4; i++)
            #pragma unroll
            for (int j = 0; j < 4; j++) acc[i][j] += a[i] * bv[j];
    }
    const float scale = 0.125f;  // 1/sqrt(64)
    const float* rb = rel_bias + h * (2 * MREL - 1);
    #pragma unroll
    for (int i = 0; i < 4; i++) {
        int q = q0 + ty * 4 + i;
        long long rowoff = ((long long)bh * Ll + q) * Ll;
        #pragma unroll
        for (int j = 0; j < 4; j++) {
            int k = k0 + tx * 4 + j;
            int ctx = q - k;
            ctx = ctx < -(MREL - 1) ? -(MREL - 1) : (ctx > (MREL - 1) ? (MREL - 1) : ctx);
            attn[rowoff + k] = acc[i][j] * scale + rb[ctx + MREL - 1];
        }
    }
}

// ---------------- Softmax in-place over last dim (2048) ----------------
__global__ void softmax_kernel(float* __restrict__ attn) {
    long long row = blockIdx.x;
    float4* r = reinterpret_cast<float4*>(attn + row * Ll);
    int t = threadIdx.x; // 256; 512 float4 per row
    float4 v0 = r[t], v1 = r[t + 256];
    float m = fmaxf(fmaxf(fmaxf(v0.x, v0.y), fmaxf(v0.z, v0.w)),
                    fmaxf(fmaxf(v1.x, v1.y), fmaxf(v1.z, v1.w)));
    __shared__ float red[256];
    red[t] = m;
    __syncthreads();
    #pragma unroll
    for (int o = 128; o > 0; o >>= 1) { if (t < o) red[t] = fmaxf(red[t], red[t + o]); __syncthreads(); }
    float rowmax = red[0];
    __syncthreads();
    v0.x = expf(v0.x - rowmax); v0.y = expf(v0.y - rowmax);
    v0.z = expf(v0.z - rowmax); v0.w = expf(v0.w - rowmax);
    v1.x = expf(v1.x - rowmax); v1.y = expf(v1.y - rowmax);
    v1.z = expf(v1.z - rowmax); v1.w = expf(v1.w - rowmax);
    red[t] = v0.x + v0.y + v0.z + v0.w + v1.x + v1.y + v1.z + v1.w;
    __syncthreads();
    #pragma unroll
    for (int o = 128; o > 0; o >>= 1) { if (t < o) red[t] += red[t + o]; __syncthreads(); }
    float inv = 1.0f / red[0];
    v0.x *= inv; v0.y *= inv; v0.z *= inv; v0.w *= inv;
    v1.x *= inv; v1.y *= inv; v1.z *= inv; v1.w *= inv;
    r[t] = v0; r[t + 256] = v1;
}

// ---------------- AV: o[b,q,h,:] = attn[b,h,q,:] @ V[b,:,h,:] ----------------
// per (b,h): M=2048(q) x N=64(d), K=2048. BM=64, BN=64, BK=16.
__global__ void av_kernel(const float* __restrict__ attn, const float* __restrict__ qkv,
                          float* __restrict__ o) {
    int bh = blockIdx.z;
    int b = bh >> 3, h = bh & 7;
    int q0 = blockIdx.x * 64;
    __shared__ float As[16][64];
    __shared__ float Vs[16][68];
    int tid = threadIdx.x;
    int ty = tid >> 4, tx = tid & 15;
    float acc[4][4] = {};
    const long long attnBase = ((long long)bh * Ll + q0) * Ll;
    const long long vBase = (long long)b * Ll * D3 + 2 * Dd + h * HD;
    for (int k0 = 0; k0 < Ll; k0 += 16) {
        #pragma unroll
        for (int i = 0; i < 4; i++) {
            int idx = tid + i * 256;
            int m = idx >> 4, kk = idx & 15;
            As[kk][m] = attn[attnBase + (long long)m * Ll + k0 + kk];
        }
        {
            int kk = tid >> 6, d = tid & 63;  // 256 threads load 4 rows x 64
            #pragma unroll
            for (int i = 0; i < 4; i++)
                Vs[kk + i * 4][d] = qkv[vBase + (long long)(k0 + kk + i * 4) * D3 + d];
        }
        __syncthreads();
        #pragma unroll
        for (int kk = 0; kk < 16; kk++) {
            float a[4], bv[4];
            #pragma unroll
            for (int i = 0; i < 4; i++) a[i]  = As[kk][ty * 4 + i];
            #pragma unroll
            for (int j = 0; j < 4; j++) bv[j] = Vs[kk][tx * 4 + j];
            #pragma unroll
            for (int i = 0; i < 4; i++)
                #pragma unroll
                for (int j = 0; j < 4; j++) acc[i][j] += a[i] * bv[j];
        }
        __syncthreads();
    }
    #pragma unroll
    for (int i = 0; i < 4; i++) {
        long long q = q0 + ty * 4 + i;
        #pragma unroll
        for (int j = 0; j < 4; j++) {
            int d = tx * 4 + j;
            o[((long long)b * Ll + q) * Dd + h * HD + d] = acc[i][j];
        }
    }
}

// ---------------- Elementwise: out = x + y * gamma[i % D] ----------------
__global__ void add_scaled_kernel(float* __restrict__ out, const float* __restrict__ x,
                                  const float* __restrict__ y, const float* __restrict__ g) {
    int i = blockIdx.x * 256 + threadIdx.x;
    out[i] = x[i] + y[i] * g[i & (Dd - 1)];
}

// ---------------- GEGLU: f = gelu_exact(bgate) * a ----------------
__global__ void geglu_kernel(const float* __restrict__ ab, float* __restrict__ f) {
    int i = blockIdx.x * 256 + threadIdx.x;  // over BL*DH
    int row = i >> 11;        // /2048
    int j = i & 2047;
    float a  = ab[((long long)row << 12) + j];
    float bg = ab[((long long)row << 12) + DH + j];
    float gelu = 0.5f * bg * (1.0f + erff(bg * 0.70710678118654752f));
    f[i] = gelu * a;
}

extern "C" void kernel_launch(void* const* d_in, const int* in_sizes, int n_in,
                              void* d_out, int out_size) {
    const float* x        = (const float*)d_in[0];
    const float* ln1_w    = (const float*)d_in[1];
    const float* ln1_b    = (const float*)d_in[2];
    const float* qkv_w    = (const float*)d_in[3];
    const float* qkv_b    = (const float*)d_in[4];
    const float* out_w    = (const float*)d_in[5];
    const float* out_b    = (const float*)d_in[6];
    const float* rel_bias = (const float*)d_in[7];
    const float* gamma1   = (const float*)d_in[8];
    const float* ln2_w    = (const float*)d_in[9];
    const float* ln2_b    = (const float*)d_in[10];
    const float* ffn_in_w = (const float*)d_in[11];
    const float* ffn_in_b = (const float*)d_in[12];
    const float* ffn_out_w= (const float*)d_in[13];
    const float* ffn_out_b= (const float*)d_in[14];
    const float* gamma2   = (const float*)d_in[15];

    float* out_x = (float*)d_out;
    float* attn  = (float*)d_out + XSIZE;

    float *h, *qkv, *o, *proj, *x1, *ab, *f;
    cudaGetSymbolAddress((void**)&h,    g_h);
    cudaGetSymbolAddress((void**)&qkv,  g_qkv);
    cudaGetSymbolAddress((void**)&o,    g_o);
    cudaGetSymbolAddress((void**)&proj, g_proj);
    cudaGetSymbolAddress((void**)&x1,   g_x1);
    cudaGetSymbolAddress((void**)&ab,   g_ab);
    cudaGetSymbolAddress((void**)&f,    g_f);

    // 1. h = LN1(x)
    ln_kernel<<<BL, 256>>>(x, ln1_w, ln1_b, h);
    // 2. qkv = h @ qkv_w + qkv_b    (4096 x 1536 x 512)
    gemm_bias_kernel<<<dim3(D3 / 64, BL / 64), 256>>>(h, qkv_w, qkv_b, qkv, D3, Dd);
    // 3. scores + rel bias -> attn buffer (pre-softmax)
    score_kernel<<<dim3(Ll / 64, Ll / 64, Bb * Hh), 256>>>(qkv, rel_bias, attn);
    // 4. softmax in place
    softmax_kernel<<<Bb * Hh * Ll, 256>>>(attn);
    // 5. o = attn @ v
    av_kernel<<<dim3(Ll / 64, 1, Bb * Hh), 256>>>(attn, qkv, o);
    // 6. proj = o @ out_w + out_b   (4096 x 512 x 512)
    gemm_bias_kernel<<<dim3(Dd / 64, BL / 64), 256>>>(o, out_w, out_b, proj, Dd, Dd);
    // 7. x1 = x + proj * gamma1
    add_scaled_kernel<<<(int)(XSIZE / 256), 256>>>(x1, x, proj, gamma1);
    // 8. h = LN2(x1)
    ln_kernel<<<BL, 256>>>(x1, ln2_w, ln2_b, h);
    // 9. ab = h @ ffn_in_w + b      (4096 x 4096 x 512)
    gemm_bias_kernel<<<dim3(2 * DH / 64, BL / 64), 256>>>(h, ffn_in_w, ffn_in_b, ab, 2 * DH, Dd);
    // 10. f = gelu(bgate) * a
    geglu_kernel<<<BL * DH / 256, 256>>>(ab, f);
    // 11. proj = f @ ffn_out_w + b  (4096 x 512 x 2048)
    gemm_bias_kernel<<<dim3(Dd / 64, BL / 64), 256>>>(f, ffn_out_w, ffn_out_b, proj, Dd, DH);
    // 12. out_x = x1 + proj * gamma2
    add_scaled_kernel<<<(int)(XSIZE / 256), 256>>>(out_x, x1, proj, gamma2);
}

// round 2
// speedup vs baseline: 4.1659x; 4.1659x over previous
#include <cuda_runtime.h>
#include <cuda_fp16.h>
#include <math.h>
#include <stdint.h>

// Problem constants
constexpr int Bb  = 2;
constexpr int Ll  = 2048;
constexpr int Dd  = 512;
constexpr int Hh  = 8;
constexpr int HD  = 64;
constexpr int DH  = 2048;
constexpr int MREL = 128;
constexpr int D3  = 3 * Dd;    // 1536
constexpr int BL  = Bb * Ll;   // 4096
constexpr long long XSIZE  = (long long)BL * Dd;
constexpr long long ATTN_N = (long long)Bb * Hh * Ll * Ll;  // 67,108,864

// fp16 staging buffers
__device__ __half g_h16  [BL * Dd];
__device__ __half g_qkv16[BL * D3];
__device__ __half g_o16  [BL * Dd];
__device__ __half g_f16  [BL * DH];
__device__ __half g_attn16[ATTN_N];            // 134 MB
// fp16 weights: qkv_w | out_w | ffn_in_w | ffn_out_w
constexpr long long OFF_QKVW   = 0;                          // 512*1536
constexpr long long OFF_OUTW   = OFF_QKVW  + (long long)Dd * D3;
constexpr long long OFF_FFNIN  = OFF_OUTW  + (long long)Dd * Dd;
constexpr long long OFF_FFNOUT = OFF_FFNIN + (long long)Dd * 2 * DH;
constexpr long long W16_TOTAL  = OFF_FFNOUT + (long long)DH * Dd;
__device__ __half g_w16[W16_TOTAL];
// fp32 scratch
__device__ float g_proj[BL * Dd];
__device__ float g_x1  [BL * Dd];
__device__ float g_ab  [BL * 2 * DH];

// ---------------- helpers ----------------
static __device__ __forceinline__ uint32_t sm32(const void* p) {
    return (uint32_t)__cvta_generic_to_shared(p);
}
static __device__ __forceinline__ void ldsm_x4(uint32_t& r0, uint32_t& r1, uint32_t& r2, uint32_t& r3, uint32_t a) {
    asm volatile("ldmatrix.sync.aligned.m8n8.x4.shared.b16 {%0,%1,%2,%3}, [%4];\n"
                 : "=r"(r0), "=r"(r1), "=r"(r2), "=r"(r3) : "r"(a));
}
static __device__ __forceinline__ void ldsm_x2(uint32_t& r0, uint32_t& r1, uint32_t a) {
    asm volatile("ldmatrix.sync.aligned.m8n8.x2.shared.b16 {%0,%1}, [%2];\n"
                 : "=r"(r0), "=r"(r1) : "r"(a));
}
static __device__ __forceinline__ void ldsm_x2t(uint32_t& r0, uint32_t& r1, uint32_t a) {
    asm volatile("ldmatrix.sync.aligned.m8n8.x2.trans.shared.b16 {%0,%1}, [%2];\n"
                 : "=r"(r0), "=r"(r1) : "r"(a));
}
static __device__ __forceinline__ void mma16(float* c, const uint32_t* a, const uint32_t* b) {
    asm volatile("mma.sync.aligned.m16n8k16.row.col.f32.f16.f16.f32 "
                 "{%0,%1,%2,%3}, {%4,%5,%6,%7}, {%8,%9}, {%0,%1,%2,%3};\n"
                 : "+f"(c[0]), "+f"(c[1]), "+f"(c[2]), "+f"(c[3])
                 : "r"(a[0]), "r"(a[1]), "r"(a[2]), "r"(a[3]), "r"(b[0]), "r"(b[1]));
}

template <typename T> __device__ __forceinline__ T cvt_out(float v);
template <> __device__ __forceinline__ float  cvt_out<float >(float v) { return v; }
template <> __device__ __forceinline__ __half cvt_out<__half>(float v) { return __float2half(v); }

// ---------------- fp32 -> fp16 convert ----------------
__global__ void f2h_kernel(const float* __restrict__ src, __half* __restrict__ dst, long long n) {
    long long i = (long long)blockIdx.x * blockDim.x + threadIdx.x;
    if (i < n) dst[i] = __float2half(src[i]);
}

// ---------------- LayerNorm -> fp16 out ----------------
__global__ void ln_kernel(const float* __restrict__ x, const float* __restrict__ w,
                          const float* __restrict__ b, __half* __restrict__ out) {
    int row = blockIdx.x;
    const float* xr = x + (long long)row * Dd;
    int t = threadIdx.x; // 256
    float v0 = xr[t], v1 = xr[t + 256];
    __shared__ float red[256];
    red[t] = v0 + v1;
    __syncthreads();
    #pragma unroll
    for (int o = 128; o > 0; o >>= 1) { if (t < o) red[t] += red[t + o]; __syncthreads(); }
    float mu = red[0] * (1.0f / Dd);
    __syncthreads();
    float d0 = v0 - mu, d1 = v1 - mu;
    red[t] = d0 * d0 + d1 * d1;
    __syncthreads();
    #pragma unroll
    for (int o = 128; o > 0; o >>= 1) { if (t < o) red[t] += red[t + o]; __syncthreads(); }
    float rstd = rsqrtf(red[0] * (1.0f / Dd) + 1e-5f);
    __half* orow = out + (long long)row * Dd;
    orow[t]       = __float2half(d0 * rstd * w[t]       + b[t]);
    orow[t + 256] = __float2half(d1 * rstd * w[t + 256] + b[t + 256]);
}

// ---------------- Tensor-core GEMM: C[M,N] = A[M,K]@W[K,N] + bias ----------------
// BM=128 BN=128 BK=32, 256 threads (8 warps: warp_m in {0,1} x warp_n in {0..3})
template <typename OutT>
__global__ void gemm16_kernel(const __half* __restrict__ A, const __half* __restrict__ W,
                              const float* __restrict__ bias, OutT* __restrict__ C,
                              int M, int N, int K) {
    __shared__ __half As[128][40];
    __shared__ __half Bs[32][136];
    int bm = blockIdx.y * 128, bn = blockIdx.x * 128;
    int tid = threadIdx.x, lane = tid & 31, wid = tid >> 5;
    int wm0 = (wid & 1) * 64, wn0 = (wid >> 1) * 32;
    float acc[4][4][4] = {};
    for (int k0 = 0; k0 < K; k0 += 32) {
        #pragma unroll
        for (int i = 0; i < 2; i++) {
            int t = tid + i * 256;
            int r = t >> 2, s = t & 3;
            *(uint4*)&As[r][s * 8] = *(const uint4*)(A + (size_t)(bm + r) * K + k0 + s * 8);
        }
        #pragma unroll
        for (int i = 0; i < 2; i++) {
            int t = tid + i * 256;
            int r = t >> 4, s = t & 15;
            *(uint4*)&Bs[r][s * 8] = *(const uint4*)(W + (size_t)(k0 + r) * N + bn + s * 8);
        }
        __syncthreads();
        #pragma unroll
        for (int ks = 0; ks < 32; ks += 16) {
            uint32_t a[4][4], b[4][2];
            #pragma unroll
            for (int i = 0; i < 4; i++)
                ldsm_x4(a[i][0], a[i][1], a[i][2], a[i][3],
                        sm32(&As[wm0 + i * 16 + (lane & 15)][ks + (lane >> 4) * 8]));
            #pragma unroll
            for (int j = 0; j < 4; j++)
                ldsm_x2t(b[j][0], b[j][1], sm32(&Bs[ks + (lane & 15)][wn0 + j * 8]));
            #pragma unroll
            for (int i = 0; i < 4; i++)
                #pragma unroll
                for (int j = 0; j < 4; j++) mma16(acc[i][j], a[i], b[j]);
        }
        __syncthreads();
    }
    #pragma unroll
    for (int i = 0; i < 4; i++) {
        #pragma unroll
        for (int j = 0; j < 4; j++) {
            int r = bm + wm0 + i * 16 + (lane >> 2);
            int c = bn + wn0 + j * 8 + (lane & 3) * 2;
            C[(size_t)r * N + c]           = cvt_out<OutT>(acc[i][j][0] + bias[c]);
            C[(size_t)r * N + c + 1]       = cvt_out<OutT>(acc[i][j][1] + bias[c + 1]);
            C[(size_t)(r + 8) * N + c]     = cvt_out<OutT>(acc[i][j][2] + bias[c]);
            C[(size_t)(r + 8) * N + c + 1] = cvt_out<OutT>(acc[i][j][3] + bias[c + 1]);
        }
    }
}

// ---------------- Scores: S = scale*(Q K^T) + rel_bias -> fp32 attn ----------------
// Block: 128q x 128k per (b,h). 8 warps: warp_m {0..3} x warp_n {0,1}.
__global__ void score16_kernel(const __half* __restrict__ qkv, const float* __restrict__ rel_bias,
                               float* __restrict__ attn) {
    int bh = blockIdx.z, b = bh >> 3, h = bh & 7;
    int q0 = blockIdx.y * 128, k0 = blockIdx.x * 128;
    __shared__ __half Qs[128][72];
    __shared__ __half Ks[128][72];
    __shared__ float rb_s[2 * MREL - 1];
    int tid = threadIdx.x, lane = tid & 31, wid = tid >> 5;
    if (tid < 2 * MREL - 1) rb_s[tid] = rel_bias[h * (2 * MREL - 1) + tid];
    const __half* Qg = qkv + (size_t)b * Ll * D3 + h * HD;
    const __half* Kg = Qg + Dd;
    #pragma unroll
    for (int i = 0; i < 4; i++) {
        int t = tid + i * 256;
        int r = t >> 3, s = t & 7;
        *(uint4*)&Qs[r][s * 8] = *(const uint4*)(Qg + (size_t)(q0 + r) * D3 + s * 8);
        *(uint4*)&Ks[r][s * 8] = *(const uint4*)(Kg + (size_t)(k0 + r) * D3 + s * 8);
    }
    __syncthreads();
    int wm0 = (wid >> 1) * 32, wn0 = (wid & 1) * 64;
    float acc[2][8][4] = {};
    #pragma unroll
    for (int ks = 0; ks < 64; ks += 16) {
        uint32_t a[2][4], bfr[8][2];
        #pragma unroll
        for (int i = 0; i < 2; i++)
            ldsm_x4(a[i][0], a[i][1], a[i][2], a[i][3],
                    sm32(&Qs[wm0 + i * 16 + (lane & 15)][ks + (lane >> 4) * 8]));
        #pragma unroll
        for (int j = 0; j < 8; j++)
            ldsm_x2(bfr[j][0], bfr[j][1],
                    sm32(&Ks[wn0 + j * 8 + (lane & 7)][ks + ((lane >> 3) & 1) * 8]));
        #pragma unroll
        for (int i = 0; i < 2; i++)
            #pragma unroll
            for (int j = 0; j < 8; j++) mma16(acc[i][j], a[i], bfr[j]);
    }
    const float scale = 0.125f;
    #pragma unroll
    for (int i = 0; i < 2; i++) {
        #pragma unroll
        for (int j = 0; j < 8; j++) {
            int q = q0 + wm0 + i * 16 + (lane >> 2);
            int kk = k0 + wn0 + j * 8 + (lane & 3) * 2;
            #pragma unroll
            for (int half_ = 0; half_ < 2; half_++) {
                int qq = q + half_ * 8;
                size_t row = ((size_t)bh * Ll + qq) * Ll;
                #pragma unroll
                for (int cc = 0; cc < 2; cc++) {
                    int kkk = kk + cc;
                    int d = qq - kkk;
                    d = d < -(MREL - 1) ? -(MREL - 1) : (d > (MREL - 1) ? (MREL - 1) : d);
                    attn[row + kkk] = acc[i][j][half_ * 2 + cc] * scale + rb_s[d + MREL - 1];
                }
            }
        }
    }
}

// ---------------- Softmax in-place (fp32) + fp16 copy ----------------
__global__ void softmax_kernel(float* __restrict__ attn, __half* __restrict__ attn16) {
    long long row = blockIdx.x;
    float4* r = reinterpret_cast<float4*>(attn + row * Ll);
    __half2* r16 = reinterpret_cast<__half2*>(attn16 + row * Ll);
    int t = threadIdx.x; // 256
    float4 v0 = r[t], v1 = r[t + 256];
    float m = fmaxf(fmaxf(fmaxf(v0.x, v0.y), fmaxf(v0.z, v0.w)),
                    fmaxf(fmaxf(v1.x, v1.y), fmaxf(v1.z, v1.w)));
    __shared__ float red[256];
    red[t] = m;
    __syncthreads();
    #pragma unroll
    for (int o = 128; o > 0; o >>= 1) { if (t < o) red[t] = fmaxf(red[t], red[t + o]); __syncthreads(); }
    float rowmax = red[0];
    __syncthreads();
    v0.x = expf(v0.x - rowmax); v0.y = expf(v0.y - rowmax);
    v0.z = expf(v0.z - rowmax); v0.w = expf(v0.w - rowmax);
    v1.x = expf(v1.x - rowmax); v1.y = expf(v1.y - rowmax);
    v1.z = expf(v1.z - rowmax); v1.w = expf(v1.w - rowmax);
    red[t] = v0.x + v0.y + v0.z + v0.w + v1.x + v1.y + v1.z + v1.w;
    __syncthreads();
    #pragma unroll
    for (int o = 128; o > 0; o >>= 1) { if (t < o) red[t] += red[t + o]; __syncthreads(); }
    float inv = 1.0f / red[0];
    v0.x *= inv; v0.y *= inv; v0.z *= inv; v0.w *= inv;
    v1.x *= inv; v1.y *= inv; v1.z *= inv; v1.w *= inv;
    r[t] = v0; r[t + 256] = v1;
    r16[t * 2]           = __floats2half2_rn(v0.x, v0.y);
    r16[t * 2 + 1]       = __floats2half2_rn(v0.z, v0.w);
    r16[(t + 256) * 2]     = __floats2half2_rn(v1.x, v1.y);
    r16[(t + 256) * 2 + 1] = __floats2half2_rn(v1.z, v1.w);
}

// ---------------- AV: o16[b,q,h,:] = attn16[b,h,q,:] @ V16[b,:,h,:] ----------------
// Block: 128q x 64d per (b,h), k-loop 64. 8 warps each 16 q rows.
__global__ void av16_kernel(const __half* __restrict__ attn16, const __half* __restrict__ qkv,
                            __half* __restrict__ o16) {
    int bh = blockIdx.z, b = bh >> 3, h = bh & 7;
    int q0 = blockIdx.x * 128;
    __shared__ __half As[128][72];
    __shared__ __half Vs[64][72];
    int tid = threadIdx.x, lane = tid & 31, wid = tid >> 5;
    int wm0 = wid * 16;
    float acc[8][4] = {};
    const __half* Ag = attn16 + ((size_t)bh * Ll + q0) * Ll;
    const __half* Vg = qkv + (size_t)b * Ll * D3 + 2 * Dd + h * HD;
    for (int t0 = 0; t0 < Ll; t0 += 64) {
        #pragma unroll
        for (int i = 0; i < 4; i++) {
            int t = tid + i * 256;
            int r = t >> 3, s = t & 7;
            *(uint4*)&As[r][s * 8] = *(const uint4*)(Ag + (size_t)r * Ll + t0 + s * 8);
        }
        #pragma unroll
        for (int i = 0; i < 2; i++) {
            int t = tid + i * 256;
            int r = t >> 3, s = t & 7;
            *(uint4*)&Vs[r][s * 8] = *(const uint4*)(Vg + (size_t)(t0 + r) * D3 + s * 8);
        }
        __syncthreads();
        #pragma unroll
        for (int ks = 0; ks < 64; ks += 16) {
            uint32_t a[4], bfr[8][2];
            ldsm_x4(a[0], a[1], a[2], a[3],
                    sm32(&As[wm0 + (lane & 15)][ks + (lane >> 4) * 8]));
            #pragma unroll
            for (int j = 0; j < 8; j++)
                ldsm_x2t(bfr[j][0], bfr[j][1], sm32(&Vs[ks + (lane & 15)][j * 8]));
            #pragma unroll
            for (int j = 0; j < 8; j++) mma16(acc[j], a, bfr[j]);
        }
        __syncthreads();
    }
    #pragma unroll
    for (int j = 0; j < 8; j++) {
        int q = q0 + wm0 + (lane >> 2);
        int c = j * 8 + (lane & 3) * 2;
        __half* dst = o16 + (size_t)(b * Ll + q) * Dd + h * HD + c;
        dst[0] = __float2half(acc[j][0]);
        dst[1] = __float2half(acc[j][1]);
        dst += (size_t)8 * Dd;
        dst[0] = __float2half(acc[j][2]);
        dst[1] = __float2half(acc[j][3]);
    }
}

// ---------------- Elementwise: out = x + y * gamma ----------------
__global__ void add_scaled_kernel(float* __restrict__ out, const float* __restrict__ x,
                                  const float* __restrict__ y, const float* __restrict__ g) {
    int i = blockIdx.x * 256 + threadIdx.x;
    out[i] = x[i] + y[i] * g[i & (Dd - 1)];
}

// ---------------- GEGLU: f16 = gelu_exact(bgate) * a ----------------
__global__ void geglu_kernel(const float* __restrict__ ab, __half* __restrict__ f) {
    int i = blockIdx.x * 256 + threadIdx.x;  // over BL*DH
    int row = i >> 11;
    int j = i & 2047;
    float a  = ab[((long long)row << 12) + j];
    float bg = ab[((long long)row << 12) + DH + j];
    float gelu = 0.5f * bg * (1.0f + erff(bg * 0.70710678118654752f));
    f[i] = __float2half(gelu * a);
}

extern "C" void kernel_launch(void* const* d_in, const int* in_sizes, int n_in,
                              void* d_out, int out_size) {
    const float* x        = (const float*)d_in[0];
    const float* ln1_w    = (const float*)d_in[1];
    const float* ln1_b    = (const float*)d_in[2];
    const float* qkv_w    = (const float*)d_in[3];
    const float* qkv_b    = (const float*)d_in[4];
    const float* out_w    = (const float*)d_in[5];
    const float* out_b    = (const float*)d_in[6];
    const float* rel_bias = (const float*)d_in[7];
    const float* gamma1   = (const float*)d_in[8];
    const float* ln2_w    = (const float*)d_in[9];
    const float* ln2_b    = (const float*)d_in[10];
    const float* ffn_in_w = (const float*)d_in[11];
    const float* ffn_in_b = (const float*)d_in[12];
    const float* ffn_out_w= (const float*)d_in[13];
    const float* ffn_out_b= (const float*)d_in[14];
    const float* gamma2   = (const float*)d_in[15];

    float* out_x = (float*)d_out;
    float* attn  = (float*)d_out + XSIZE;

    __half *h16, *qkv16, *o16, *f16, *attn16, *w16;
    float *proj, *x1, *ab;
    cudaGetSymbolAddress((void**)&h16,    g_h16);
    cudaGetSymbolAddress((void**)&qkv16,  g_qkv16);
    cudaGetSymbolAddress((void**)&o16,    g_o16);
    cudaGetSymbolAddress((void**)&f16,    g_f16);
    cudaGetSymbolAddress((void**)&attn16, g_attn16);
    cudaGetSymbolAddress((void**)&w16,    g_w16);
    cudaGetSymbolAddress((void**)&proj,   g_proj);
    cudaGetSymbolAddress((void**)&x1,     g_x1);
    cudaGetSymbolAddress((void**)&ab,     g_ab);

    // 0. convert weights to fp16
    f2h_kernel<<<(int)(((long long)Dd * D3 + 255) / 256), 256>>>(qkv_w,    w16 + OFF_QKVW,   (long long)Dd * D3);
    f2h_kernel<<<(int)(((long long)Dd * Dd + 255) / 256), 256>>>(out_w,    w16 + OFF_OUTW,   (long long)Dd * Dd);
    f2h_kernel<<<(int)(((long long)Dd * 2 * DH + 255) / 256), 256>>>(ffn_in_w, w16 + OFF_FFNIN, (long long)Dd * 2 * DH);
    f2h_kernel<<<(int)(((long long)DH * Dd + 255) / 256), 256>>>(ffn_out_w, w16 + OFF_FFNOUT, (long long)DH * Dd);

    // 1. h16 = LN1(x)
    ln_kernel<<<BL, 256>>>(x, ln1_w, ln1_b, h16);
    // 2. qkv16 = h16 @ qkv_w + qkv_b   (4096 x 1536 x 512)
    gemm16_kernel<__half><<<dim3(D3 / 128, BL / 128), 256>>>(h16, w16 + OFF_QKVW, qkv_b, qkv16, BL, D3, Dd);
    // 3. scores + rel bias -> attn (fp32, pre-softmax)
    score16_kernel<<<dim3(Ll / 128, Ll / 128, Bb * Hh), 256>>>(qkv16, rel_bias, attn);
    // 4. softmax in place + fp16 copy
    softmax_kernel<<<Bb * Hh * Ll, 256>>>(attn, attn16);
    // 5. o16 = attn16 @ v16
    av16_kernel<<<dim3(Ll / 128, 1, Bb * Hh), 256>>>(attn16, qkv16, o16);
    // 6. proj = o16 @ out_w + out_b    (4096 x 512 x 512)
    gemm16_kernel<float><<<dim3(Dd / 128, BL / 128), 256>>>(o16, w16 + OFF_OUTW, out_b, proj, BL, Dd, Dd);
    // 7. x1 = x + proj * gamma1
    add_scaled_kernel<<<(int)(XSIZE / 256), 256>>>(x1, x, proj, gamma1);
    // 8. h16 = LN2(x1)
    ln_kernel<<<BL, 256>>>(x1, ln2_w, ln2_b, h16);
    // 9. ab = h16 @ ffn_in_w + b       (4096 x 4096 x 512)
    gemm16_kernel<float><<<dim3(2 * DH / 128, BL / 128), 256>>>(h16, w16 + OFF_FFNIN, ffn_in_b, ab, BL, 2 * DH, Dd);
    // 10. f16 = gelu(bgate) * a
    geglu_kernel<<<BL * DH / 256, 256>>>(ab, f16);
    // 11. proj = f16 @ ffn_out_w + b   (4096 x 512 x 2048)
    gemm16_kernel<float><<<dim3(Dd / 128, BL / 128), 256>>>(f16, w16 + OFF_FFNOUT, ffn_out_b, proj, BL, Dd, DH);
    // 12. out_x = x1 + proj * gamma2
    add_scaled_kernel<<<(int)(XSIZE / 256), 256>>>(out_x, x1, proj, gamma2);
}